// round 1
// baseline (speedup 1.0000x reference)
#include <cuda_runtime.h>
#include <cuda_bf16.h>

#define BOLTZMAN 0.001987191f
#define L 64

// Coefficient scratch (allocation-free: __device__ globals)
__device__ float g_cA[L];      // cA[s] = -mk[64-s], s=1..63 ; cA[0]=0
__device__ float g_cB[L];      // cB[s] =  h[64-s],  s=1..63 ; cB[0]=0
__device__ float g_sc[2];      // [0] = -mk[0] (coeff for v), [1] = h[0] (coeff for w_new)

// Kernel 1: build coefficients. 1 block, 64 threads. O(L^2) tiny.
__global__ void gle_coef_kernel(const float* __restrict__ h,
                                const int* __restrict__ Traw,
                                const float* __restrict__ mass) {
    __shared__ float hs[L];
    int k = threadIdx.x;           // 0..63 = autocorrelation lag
    hs[k] = h[k];
    __syncthreads();

    float mk = 0.0f;
    #pragma unroll 8
    for (int j = 0; j + k < L; ++j) mk += hs[j] * hs[j + k];

    // T is a python int -> expect int32; fall back to float bits if implausible
    int ti = Traw[0];
    float T = (ti > 0 && ti < 10000000) ? (float)ti : __int_as_float(ti);
    float scale = mass[0] * BOLTZMAN * T;
    mk *= scale;

    if (k == 0) {
        g_sc[0] = -mk;     // multiplies v[c]      (mk[0] term)
        g_sc[1] = hs[0];   // multiplies w_new[c]  (h[0] term)
        g_cA[0] = 0.0f;
        g_cB[0] = 0.0f;
    } else {
        g_cA[L - k] = -mk;     // cA[s] = -mk[64-s]
        g_cB[L - k] = hs[k];   // cB[s] =  h[64-s]
    }
}

// Kernel 2: streaming dot products.
// 16 threads per channel; each thread loads one float4 (16B) of the 256B row
// from v_list and w_list -> fully coalesced. Width-16 shuffle reduction.
__global__ void __launch_bounds__(256) gle_main_kernel(
    const float* __restrict__ v,
    const float* __restrict__ vlist,
    const float* __restrict__ wlist,
    const float* __restrict__ wnew,
    float* __restrict__ out,
    int nch) {
    __shared__ float sA[L];
    __shared__ float sB[L];
    __shared__ float sS[2];

    int tid = threadIdx.x;
    if (tid < L)                sA[tid]      = g_cA[tid];
    else if (tid < 2 * L)       sB[tid - L]  = g_cB[tid - L];
    if (tid < 2)                sS[tid]      = g_sc[tid];
    __syncthreads();

    int c = blockIdx.x * 16 + (tid >> 4);   // channel
    int q = tid & 15;                       // float4 index within 64-float row
    bool valid = (c < nch);
    int cc = valid ? c : (nch - 1);         // clamp so all lanes stay active for shfl

    const float4 a  = ((const float4*)vlist)[(long long)cc * 16 + q];
    const float4 b  = ((const float4*)wlist)[(long long)cc * 16 + q];
    const float4 ca = ((const float4*)sA)[q];
    const float4 cb = ((const float4*)sB)[q];

    float acc = a.x * ca.x + a.y * ca.y + a.z * ca.z + a.w * ca.w
              + b.x * cb.x + b.y * cb.y + b.z * cb.z + b.w * cb.w;

    // reduce across the 16 lanes of this half-warp-half
    acc += __shfl_down_sync(0xffffffffu, acc, 8, 16);
    acc += __shfl_down_sync(0xffffffffu, acc, 4, 16);
    acc += __shfl_down_sync(0xffffffffu, acc, 2, 16);
    acc += __shfl_down_sync(0xffffffffu, acc, 1, 16);

    if (q == 0 && valid) {
        out[c] = acc + v[c] * sS[0] + wnew[c] * sS[1];
    }
}

extern "C" void kernel_launch(void* const* d_in, const int* in_sizes, int n_in,
                              void* d_out, int out_size) {
    // metadata order: v, T, dt, mass, h, v_list, w_list, w_new
    const float* v     = (const float*)d_in[0];
    const int*   Traw  = (const int*)  d_in[1];
    // d_in[2] = dt (unused by reference)
    const float* mass  = (const float*)d_in[3];
    const float* h     = (const float*)d_in[4];
    const float* vlist = (const float*)d_in[5];
    const float* wlist = (const float*)d_in[6];
    const float* wnew  = (const float*)d_in[7];
    float* out = (float*)d_out;

    int nch = in_sizes[0];                 // 3*NATOM channels

    gle_coef_kernel<<<1, 64>>>(h, Traw, mass);

    int blocks = (nch + 15) / 16;
    gle_main_kernel<<<blocks, 256>>>(v, vlist, wlist, wnew, out, nch);
}

// round 2
// speedup vs baseline: 1.0457x; 1.0457x over previous
#include <cuda_runtime.h>
#include <cuda_bf16.h>

#define BOLTZMAN 0.001987191f
#define L 64

// Single fused kernel:
//  - every block recomputes the 64 coefficient values from h (L2-cached, 256B)
//    while its front-batched global loads are in flight
//  - 32 channels per 256-thread block; 16 lanes per channel; each thread
//    serves 2 channels -> 4 independent float4 LDGs per thread (MLP=4)
__global__ void __launch_bounds__(256) gle_fused_kernel(
    const float* __restrict__ v,
    const float* __restrict__ h,
    const int*   __restrict__ Traw,
    const float* __restrict__ mass,
    const float* __restrict__ vlist,
    const float* __restrict__ wlist,
    const float* __restrict__ wnew,
    float* __restrict__ out,
    int nch) {
    __shared__ float hs[L];
    __shared__ float sA[L];    // sA[s] = -mk[64-s] (s>=1), sA[0]=0
    __shared__ float sB[L];    // sB[s] =  h[64-s]  (s>=1), sB[0]=0
    __shared__ float sS[2];    // [0] = -mk[0], [1] = h[0]

    int tid = threadIdx.x;
    int grp = tid >> 4;                 // 0..15
    int q   = tid & 15;                 // float4 index within row

    int c0 = blockIdx.x * 32 + grp;     // channels this thread serves
    int c1 = c0 + 16;
    bool v0 = (c0 < nch), v1 = (c1 < nch);
    int cc0 = v0 ? c0 : 0, cc1 = v1 ? c1 : 0;

    // ---- front-batch the 4 big streaming loads (MLP=4, fully coalesced:
    //      a warp covers two contiguous 256B rows) ----
    const float4 a0 = ((const float4*)vlist)[(long long)cc0 * 16 + q];
    const float4 b0 = ((const float4*)wlist)[(long long)cc0 * 16 + q];
    const float4 a1 = ((const float4*)vlist)[(long long)cc1 * 16 + q];
    const float4 b1 = ((const float4*)wlist)[(long long)cc1 * 16 + q];

    // ---- coefficient computation overlapped with the loads above ----
    if (tid < L) hs[tid] = h[tid];
    __syncthreads();
    if (tid < L) {
        int k = tid;
        float mk = 0.0f;
        #pragma unroll 8
        for (int j = 0; j + k < L; ++j) mk += hs[j] * hs[j + k];
        int ti = Traw[0];
        float T = (ti > 0 && ti < 10000000) ? (float)ti : __int_as_float(ti);
        mk *= mass[0] * BOLTZMAN * T;
        if (k == 0) {
            sS[0] = -mk;
            sS[1] = hs[0];
            sA[0] = 0.0f;
            sB[0] = 0.0f;
        } else {
            sA[L - k] = -mk;
            sB[L - k] = hs[k];
        }
    }
    __syncthreads();

    const float4 ca = ((const float4*)sA)[q];
    const float4 cb = ((const float4*)sB)[q];

    float acc0 = a0.x * ca.x + a0.y * ca.y + a0.z * ca.z + a0.w * ca.w
               + b0.x * cb.x + b0.y * cb.y + b0.z * cb.z + b0.w * cb.w;
    float acc1 = a1.x * ca.x + a1.y * ca.y + a1.z * ca.z + a1.w * ca.w
               + b1.x * cb.x + b1.y * cb.y + b1.z * cb.z + b1.w * cb.w;

    // width-16 reduction, both accumulators in the same shuffle chain
    acc0 += __shfl_down_sync(0xffffffffu, acc0, 8, 16);
    acc1 += __shfl_down_sync(0xffffffffu, acc1, 8, 16);
    acc0 += __shfl_down_sync(0xffffffffu, acc0, 4, 16);
    acc1 += __shfl_down_sync(0xffffffffu, acc1, 4, 16);
    acc0 += __shfl_down_sync(0xffffffffu, acc0, 2, 16);
    acc1 += __shfl_down_sync(0xffffffffu, acc1, 2, 16);
    acc0 += __shfl_down_sync(0xffffffffu, acc0, 1, 16);
    acc1 += __shfl_down_sync(0xffffffffu, acc1, 1, 16);

    if (q == 0) {
        if (v0) out[c0] = acc0 + v[c0] * sS[0] + wnew[c0] * sS[1];
        if (v1) out[c1] = acc1 + v[c1] * sS[0] + wnew[c1] * sS[1];
    }
}

extern "C" void kernel_launch(void* const* d_in, const int* in_sizes, int n_in,
                              void* d_out, int out_size) {
    // metadata order: v, T, dt, mass, h, v_list, w_list, w_new
    const float* v     = (const float*)d_in[0];
    const int*   Traw  = (const int*)  d_in[1];
    const float* mass  = (const float*)d_in[3];
    const float* h     = (const float*)d_in[4];
    const float* vlist = (const float*)d_in[5];
    const float* wlist = (const float*)d_in[6];
    const float* wnew  = (const float*)d_in[7];
    float* out = (float*)d_out;

    int nch = in_sizes[0];                 // 3*NATOM channels
    int blocks = (nch + 31) / 32;
    gle_fused_kernel<<<blocks, 256>>>(v, h, Traw, mass, vlist, wlist, wnew, out, nch);
}

// round 3
// speedup vs baseline: 1.2091x; 1.1563x over previous
#include <cuda_runtime.h>
#include <cuda_bf16.h>

#define BOLTZMAN 0.001987191f
#define L 64

// Coefficients, written by gle_coef_kernel, read via __ldg by main kernel.
__device__ __align__(16) float g_cA[L];  // g_cA[s] = -mk[64-s] (s>=1), [0]=0
__device__ __align__(16) float g_cB[L];  // g_cB[s] =  h[64-s]  (s>=1), [0]=0
__device__ float g_sc[2];                // [0] = -mk[0], [1] = h[0]

// Tiny coefficient kernel: 1 block, 64 threads.
__global__ void gle_coef_kernel(const float* __restrict__ h,
                                const int* __restrict__ Traw,
                                const float* __restrict__ mass) {
    __shared__ float hs[L];
    int k = threadIdx.x;
    hs[k] = h[k];
    __syncthreads();

    float mk = 0.0f;
    #pragma unroll 8
    for (int j = 0; j + k < L; ++j) mk += hs[j] * hs[j + k];

    int ti = Traw[0];
    float T = (ti > 0 && ti < 10000000) ? (float)ti : __int_as_float(ti);
    mk *= mass[0] * BOLTZMAN * T;

    if (k == 0) {
        g_sc[0] = -mk;
        g_sc[1] = hs[0];
        g_cA[0] = 0.0f;
        g_cB[0] = 0.0f;
    } else {
        g_cA[L - k] = -mk;
        g_cB[L - k] = hs[k];
    }
}

// Main streaming kernel: no shared memory, no __syncthreads.
// 512 threads/block, 64 channels/block (2 per thread, 16 lanes per channel).
// All loads (streaming rows, scalar terms, coefficients) are front-batched so
// the block critical path is one memory round-trip + a short epilogue.
__global__ void __launch_bounds__(512) gle_main_kernel(
    const float* __restrict__ v,
    const float* __restrict__ vlist,
    const float* __restrict__ wlist,
    const float* __restrict__ wnew,
    float* __restrict__ out,
    int nch) {
    int tid = threadIdx.x;
    int grp = tid >> 4;                 // 0..31
    int q   = tid & 15;                 // float4 index within 64-float row

    int c0 = blockIdx.x * 64 + grp;
    int c1 = c0 + 32;
    bool ok0 = (c0 < nch), ok1 = (c1 < nch);
    int cc0 = ok0 ? c0 : 0, cc1 = ok1 ? c1 : 0;

    const float4* vl4 = (const float4*)vlist;
    const float4* wl4 = (const float4*)wlist;

    // ---- front-batched streaming loads (coalesced: warp covers two 256B rows) ----
    const float4 a0 = __ldg(&vl4[(long long)cc0 * 16 + q]);
    const float4 b0 = __ldg(&wl4[(long long)cc0 * 16 + q]);
    const float4 a1 = __ldg(&vl4[(long long)cc1 * 16 + q]);
    const float4 b1 = __ldg(&wl4[(long long)cc1 * 16 + q]);

    // ---- front-batched scalar terms (only reducer lanes need them) ----
    float vv0 = 0.f, wn0 = 0.f, vv1 = 0.f, wn1 = 0.f;
    if (q == 0) {
        vv0 = __ldg(&v[cc0]);
        wn0 = __ldg(&wnew[cc0]);
        vv1 = __ldg(&v[cc1]);
        wn1 = __ldg(&wnew[cc1]);
    }

    // ---- coefficients: L2-resident after coef kernel, 2 lines per warp ----
    const float4 ca = __ldg(&((const float4*)g_cA)[q]);
    const float4 cb = __ldg(&((const float4*)g_cB)[q]);
    const float s0 = __ldg(&g_sc[0]);
    const float s1 = __ldg(&g_sc[1]);

    float acc0 = a0.x * ca.x + a0.y * ca.y + a0.z * ca.z + a0.w * ca.w
               + b0.x * cb.x + b0.y * cb.y + b0.z * cb.z + b0.w * cb.w;
    float acc1 = a1.x * ca.x + a1.y * ca.y + a1.z * ca.z + a1.w * ca.w
               + b1.x * cb.x + b1.y * cb.y + b1.z * cb.z + b1.w * cb.w;

    // width-16 reduction, interleaved for ILP
    acc0 += __shfl_down_sync(0xffffffffu, acc0, 8, 16);
    acc1 += __shfl_down_sync(0xffffffffu, acc1, 8, 16);
    acc0 += __shfl_down_sync(0xffffffffu, acc0, 4, 16);
    acc1 += __shfl_down_sync(0xffffffffu, acc1, 4, 16);
    acc0 += __shfl_down_sync(0xffffffffu, acc0, 2, 16);
    acc1 += __shfl_down_sync(0xffffffffu, acc1, 2, 16);
    acc0 += __shfl_down_sync(0xffffffffu, acc0, 1, 16);
    acc1 += __shfl_down_sync(0xffffffffu, acc1, 1, 16);

    if (q == 0) {
        if (ok0) out[c0] = acc0 + vv0 * s0 + wn0 * s1;
        if (ok1) out[c1] = acc1 + vv1 * s0 + wn1 * s1;
    }
}

extern "C" void kernel_launch(void* const* d_in, const int* in_sizes, int n_in,
                              void* d_out, int out_size) {
    // metadata order: v, T, dt, mass, h, v_list, w_list, w_new
    const float* v     = (const float*)d_in[0];
    const int*   Traw  = (const int*)  d_in[1];
    const float* mass  = (const float*)d_in[3];
    const float* h     = (const float*)d_in[4];
    const float* vlist = (const float*)d_in[5];
    const float* wlist = (const float*)d_in[6];
    const float* wnew  = (const float*)d_in[7];
    float* out = (float*)d_out;

    int nch = in_sizes[0];                 // 3*NATOM channels

    gle_coef_kernel<<<1, 64>>>(h, Traw, mass);

    int blocks = (nch + 63) / 64;
    gle_main_kernel<<<blocks, 512>>>(v, vlist, wlist, wnew, out, nch);
}

// round 4
// speedup vs baseline: 1.3040x; 1.0784x over previous
#include <cuda_runtime.h>
#include <cuda_bf16.h>

#define BOLTZMAN 0.001987191f
#define L 64

// Coefficients, written by gle_coef_kernel, read by main kernel after PDL sync.
__device__ __align__(16) float g_cA[L];  // g_cA[s] = -mk[64-s] (s>=1), [0]=0
__device__ __align__(16) float g_cB[L];  // g_cB[s] =  h[64-s]  (s>=1), [0]=0
__device__ float g_sc[2];                // [0] = -mk[0], [1] = h[0]

// Tiny coefficient kernel: 1 block, 64 threads.
__global__ void gle_coef_kernel(const float* __restrict__ h,
                                const int* __restrict__ Traw,
                                const float* __restrict__ mass) {
    __shared__ float hs[L];
    int k = threadIdx.x;
    hs[k] = h[k];
    __syncthreads();

    float mk = 0.0f;
    #pragma unroll 8
    for (int j = 0; j + k < L; ++j) mk += hs[j] * hs[j + k];

    int ti = Traw[0];
    float T = (ti > 0 && ti < 10000000) ? (float)ti : __int_as_float(ti);
    mk *= mass[0] * BOLTZMAN * T;

    if (k == 0) {
        g_sc[0] = -mk;
        g_sc[1] = hs[0];
        g_cA[0] = 0.0f;
        g_cB[0] = 0.0f;
    } else {
        g_cA[L - k] = -mk;
        g_cB[L - k] = hs[k];
    }
}

// Main streaming kernel (PDL secondary): front-batches all streaming loads,
// THEN waits on the coef kernel via cudaGridDependencySynchronize(), so the
// coef kernel + launch gap hide under this kernel's own load ramp.
// 512 threads/block, 64 channels/block (2/thread, 16 lanes/channel).
__global__ void __launch_bounds__(512) gle_main_kernel(
    const float* __restrict__ v,
    const float* __restrict__ vlist,
    const float* __restrict__ wlist,
    const float* __restrict__ wnew,
    float* __restrict__ out,
    int nch) {
    int tid = threadIdx.x;
    int grp = tid >> 4;                 // 0..31
    int q   = tid & 15;                 // float4 index within 64-float row

    int c0 = blockIdx.x * 64 + grp;
    int c1 = c0 + 32;
    bool ok0 = (c0 < nch), ok1 = (c1 < nch);
    int cc0 = ok0 ? c0 : 0, cc1 = ok1 ? c1 : 0;
    int i0 = cc0 * 16 + q;              // fits int32 (max ~9.6M float4s)
    int i1 = cc1 * 16 + q;

    const float4* vl4 = (const float4*)vlist;
    const float4* wl4 = (const float4*)wlist;

    // ---- front-batched streaming loads, evict-first (touched exactly once) ----
    const float4 a0 = __ldcs(vl4 + i0);
    const float4 b0 = __ldcs(wl4 + i0);
    const float4 a1 = __ldcs(vl4 + i1);
    const float4 b1 = __ldcs(wl4 + i1);

    // ---- front-batched scalar terms (only reducer lanes) ----
    float vv0 = 0.f, wn0 = 0.f, vv1 = 0.f, wn1 = 0.f;
    if (q == 0) {
        vv0 = __ldg(&v[cc0]);
        wn0 = __ldg(&wnew[cc0]);
        vv1 = __ldg(&v[cc1]);
        wn1 = __ldg(&wnew[cc1]);
    }

    // ---- wait for coef kernel (PDL), then read coefficients ----
    cudaGridDependencySynchronize();

    const float4 ca = __ldg(&((const float4*)g_cA)[q]);
    const float4 cb = __ldg(&((const float4*)g_cB)[q]);
    const float s0 = __ldg(&g_sc[0]);
    const float s1 = __ldg(&g_sc[1]);

    float acc0 = a0.x * ca.x + a0.y * ca.y + a0.z * ca.z + a0.w * ca.w
               + b0.x * cb.x + b0.y * cb.y + b0.z * cb.z + b0.w * cb.w;
    float acc1 = a1.x * ca.x + a1.y * ca.y + a1.z * ca.z + a1.w * ca.w
               + b1.x * cb.x + b1.y * cb.y + b1.z * cb.z + b1.w * cb.w;

    // width-16 reduction, interleaved for ILP
    acc0 += __shfl_down_sync(0xffffffffu, acc0, 8, 16);
    acc1 += __shfl_down_sync(0xffffffffu, acc1, 8, 16);
    acc0 += __shfl_down_sync(0xffffffffu, acc0, 4, 16);
    acc1 += __shfl_down_sync(0xffffffffu, acc1, 4, 16);
    acc0 += __shfl_down_sync(0xffffffffu, acc0, 2, 16);
    acc1 += __shfl_down_sync(0xffffffffu, acc1, 2, 16);
    acc0 += __shfl_down_sync(0xffffffffu, acc0, 1, 16);
    acc1 += __shfl_down_sync(0xffffffffu, acc1, 1, 16);

    if (q == 0) {
        if (ok0) out[c0] = acc0 + vv0 * s0 + wn0 * s1;
        if (ok1) out[c1] = acc1 + vv1 * s0 + wn1 * s1;
    }
}

extern "C" void kernel_launch(void* const* d_in, const int* in_sizes, int n_in,
                              void* d_out, int out_size) {
    // metadata order: v, T, dt, mass, h, v_list, w_list, w_new
    const float* v     = (const float*)d_in[0];
    const int*   Traw  = (const int*)  d_in[1];
    const float* mass  = (const float*)d_in[3];
    const float* h     = (const float*)d_in[4];
    const float* vlist = (const float*)d_in[5];
    const float* wlist = (const float*)d_in[6];
    const float* wnew  = (const float*)d_in[7];
    float* out = (float*)d_out;

    int nch = in_sizes[0];                 // 3*NATOM channels

    gle_coef_kernel<<<1, 64>>>(h, Traw, mass);

    // Main kernel with programmatic dependent launch: overlaps with coef kernel.
    int blocks = (nch + 63) / 64;

    cudaLaunchAttribute attrs[1];
    attrs[0].id = cudaLaunchAttributeProgrammaticStreamSerialization;
    attrs[0].val.programmaticStreamSerializationAllowed = 1;

    cudaLaunchConfig_t cfg = {};
    cfg.gridDim = dim3((unsigned)blocks, 1, 1);
    cfg.blockDim = dim3(512, 1, 1);
    cfg.dynamicSmemBytes = 0;
    cfg.stream = 0;            // legacy default stream (same as <<<>>>)
    cfg.attrs = attrs;
    cfg.numAttrs = 1;

    cudaLaunchKernelEx(&cfg, gle_main_kernel, v, vlist, wlist, wnew, out, nch);
}